// round 1
// baseline (speedup 1.0000x reference)
#include <cuda_runtime.h>

#define B_  4
#define T_  2048
#define C_  1024
#define H_  16
#define HS_ 64

// Scratch (allocation-free rule: __device__ globals)
__device__ float g_q[B_ * H_ * T_ * HS_];
__device__ float g_k[B_ * H_ * T_ * HS_];
__device__ float g_v[B_ * H_ * T_ * HS_];
__device__ float g_att[B_ * T_ * C_];

// ---------------------------------------------------------------------------
// QKV projection: for each (proj, head) z: out[b,h,t,:] = x[b,t,:] @ W[h]
// Tiled SGEMM 64x64, K-tile 16, 256 threads, 4x4 micro-tile per thread.
// ---------------------------------------------------------------------------
__global__ __launch_bounds__(256) void qkv_gemm_kernel(
    const float* __restrict__ x,
    const float* __restrict__ Wq,
    const float* __restrict__ Wk,
    const float* __restrict__ Wv)
{
    const int z = blockIdx.z;
    const int p = z >> 4;       // 0=q, 1=k, 2=v
    const int h = z & 15;
    const float* W = (p == 0 ? Wq : (p == 1 ? Wk : Wv)) + (size_t)h * C_ * HS_;
    float* outb = (p == 0 ? g_q : (p == 1 ? g_k : g_v));

    const int m0 = blockIdx.x * 64;
    const int b  = m0 / T_;
    const int t0 = m0 % T_;     // 64-row tile never crosses batch boundary
    float* out = outb + ((size_t)(b * H_ + h) * T_ + t0) * HS_;

    __shared__ float As[16][68];   // [kk][row], pad 68 -> <=2-way store conflicts
    __shared__ float Bs[16][68];   // [kk][n]

    const int tid = threadIdx.x;
    const int tx = tid & 15;
    const int ty = tid >> 4;

    float acc[4][4];
    #pragma unroll
    for (int i = 0; i < 4; i++)
        #pragma unroll
        for (int j = 0; j < 4; j++) acc[i][j] = 0.f;

    const int ar = tid >> 2;         // A: row 0..63
    const int ak = (tid & 3) * 4;    // A: k offset (float4)
    const int bk = tid >> 4;         // B: k row 0..15
    const int bn = (tid & 15) * 4;   // B: n offset (float4)

    for (int k0 = 0; k0 < C_; k0 += 16) {
        float4 av = *(const float4*)&x[(size_t)(m0 + ar) * C_ + k0 + ak];
        float4 bv = *(const float4*)&W[(size_t)(k0 + bk) * HS_ + bn];
        __syncthreads();
        As[ak + 0][ar] = av.x; As[ak + 1][ar] = av.y;
        As[ak + 2][ar] = av.z; As[ak + 3][ar] = av.w;
        *(float4*)&Bs[bk][bn] = bv;
        __syncthreads();
        #pragma unroll
        for (int kk = 0; kk < 16; kk++) {
            float4 a  = *(const float4*)&As[kk][ty * 4];
            float4 bb = *(const float4*)&Bs[kk][tx * 4];
            float ai[4] = {a.x, a.y, a.z, a.w};
            float bj[4] = {bb.x, bb.y, bb.z, bb.w};
            #pragma unroll
            for (int i = 0; i < 4; i++)
                #pragma unroll
                for (int j = 0; j < 4; j++)
                    acc[i][j] = fmaf(ai[i], bj[j], acc[i][j]);
        }
    }
    #pragma unroll
    for (int i = 0; i < 4; i++) {
        float4 r = make_float4(acc[i][0], acc[i][1], acc[i][2], acc[i][3]);
        *(float4*)&out[(size_t)(ty * 4 + i) * HS_ + tx * 4] = r;
    }
}

// ---------------------------------------------------------------------------
// Causal flash attention, fp32. 1 thread = 1 query row (q[64], o[64] in regs).
// K/V tiles (64 rows) staged in smem via linear float4 copy (conflict-free).
// All smem compute reads are warp-uniform -> broadcast (1 crossbar phase).
// Online softmax amortized over chunks of 8 kv elements.
// ---------------------------------------------------------------------------
__global__ __launch_bounds__(128) void attn_kernel()
{
    const int bh  = blockIdx.y;            // b*H + h
    const int r0  = blockIdx.x * 128;
    const int tid = threadIdx.x;
    const int row = r0 + tid;

    const float* Q = g_q + (size_t)bh * T_ * HS_;
    const float* K = g_k + (size_t)bh * T_ * HS_;
    const float* V = g_v + (size_t)bh * T_ * HS_;

    __shared__ float Ks[64 * 64];
    __shared__ float Vs[64 * 64];

    float q[64];
    #pragma unroll
    for (int d = 0; d < 64; d += 4) {
        float4 t = *(const float4*)&Q[(size_t)row * HS_ + d];
        q[d] = t.x; q[d + 1] = t.y; q[d + 2] = t.z; q[d + 3] = t.w;
    }
    float o[64];
    #pragma unroll
    for (int d = 0; d < 64; d++) o[d] = 0.f;
    float m = -1e30f, l = 0.f;
    const float scale = 0.125f;   // 1/sqrt(64)

    const int kv_end = r0 + 128;  // causal: nothing beyond this tile needed
    for (int j0 = 0; j0 < kv_end; j0 += 64) {
        __syncthreads();
        const float4* Kg = (const float4*)&K[(size_t)j0 * HS_];
        const float4* Vg = (const float4*)&V[(size_t)j0 * HS_];
        #pragma unroll
        for (int i = 0; i < 8; i++) {
            ((float4*)Ks)[tid + i * 128] = Kg[tid + i * 128];
            ((float4*)Vs)[tid + i * 128] = Vg[tid + i * 128];
        }
        __syncthreads();

        #pragma unroll 1
        for (int jc = 0; jc < 64; jc += 8) {
            float s[8];
            #pragma unroll
            for (int jj = 0; jj < 8; jj++) {
                const float4* kr4 = (const float4*)&Ks[(jc + jj) * 64];
                float s0 = 0.f, s1 = 0.f, s2 = 0.f, s3 = 0.f;
                #pragma unroll
                for (int d4 = 0; d4 < 16; d4++) {
                    float4 kv = kr4[d4];
                    s0 = fmaf(q[d4 * 4 + 0], kv.x, s0);
                    s1 = fmaf(q[d4 * 4 + 1], kv.y, s1);
                    s2 = fmaf(q[d4 * 4 + 2], kv.z, s2);
                    s3 = fmaf(q[d4 * 4 + 3], kv.w, s3);
                }
                float sv = ((s0 + s1) + (s2 + s3)) * scale;
                if (j0 + jc + jj > row) sv = -1e30f;   // causal mask
                s[jj] = sv;
            }
            float mc = s[0];
            #pragma unroll
            for (int jj = 1; jj < 8; jj++) mc = fmaxf(mc, s[jj]);
            float m_new = fmaxf(m, mc);
            if (m_new < -1e29f) continue;    // chunk fully masked, nothing seen
            float corr = __expf(m - m_new);
            m = m_new;
            float p[8];
            float ps = 0.f;
            #pragma unroll
            for (int jj = 0; jj < 8; jj++) {
                p[jj] = __expf(s[jj] - m);
                ps += p[jj];
            }
            l = l * corr + ps;
            #pragma unroll
            for (int d = 0; d < 64; d++) o[d] *= corr;
            #pragma unroll
            for (int jj = 0; jj < 8; jj++) {
                const float4* vr4 = (const float4*)&Vs[(jc + jj) * 64];
                float pj = p[jj];
                #pragma unroll
                for (int d4 = 0; d4 < 16; d4++) {
                    float4 vv = vr4[d4];
                    o[d4 * 4 + 0] = fmaf(pj, vv.x, o[d4 * 4 + 0]);
                    o[d4 * 4 + 1] = fmaf(pj, vv.y, o[d4 * 4 + 1]);
                    o[d4 * 4 + 2] = fmaf(pj, vv.z, o[d4 * 4 + 2]);
                    o[d4 * 4 + 3] = fmaf(pj, vv.w, o[d4 * 4 + 3]);
                }
            }
        }
    }
    // l > 0 guaranteed: the diagonal element is always unmasked.
    const float inv_l = 1.f / l;
    const int b = bh >> 4, h = bh & 15;
    float* outp = g_att + ((size_t)(b * T_ + row)) * C_ + h * HS_;
    #pragma unroll
    for (int d = 0; d < 64; d += 4) {
        float4 r = make_float4(o[d] * inv_l, o[d + 1] * inv_l,
                               o[d + 2] * inv_l, o[d + 3] * inv_l);
        *(float4*)&outp[d] = r;
    }
}

// ---------------------------------------------------------------------------
// Output projection: out = g_att @ Wo^T + bo.  Wo is [C,C] row-major, so both
// A and B tiles are K-contiguous -> identical float4 load pattern.
// ---------------------------------------------------------------------------
__global__ __launch_bounds__(256) void proj_gemm_kernel(
    const float* __restrict__ Wo,
    const float* __restrict__ bo,
    float* __restrict__ out)
{
    const int m0 = blockIdx.x * 64;
    const int n0 = blockIdx.y * 64;

    __shared__ float As[16][68];
    __shared__ float Bs[16][68];

    const int tid = threadIdx.x;
    const int tx = tid & 15;
    const int ty = tid >> 4;

    float acc[4][4];
    #pragma unroll
    for (int i = 0; i < 4; i++)
        #pragma unroll
        for (int j = 0; j < 4; j++) acc[i][j] = 0.f;

    const int ar = tid >> 2;
    const int ak = (tid & 3) * 4;

    for (int k0 = 0; k0 < C_; k0 += 16) {
        float4 av = *(const float4*)&g_att[(size_t)(m0 + ar) * C_ + k0 + ak];
        float4 bv = *(const float4*)&Wo[(size_t)(n0 + ar) * C_ + k0 + ak];
        __syncthreads();
        As[ak + 0][ar] = av.x; As[ak + 1][ar] = av.y;
        As[ak + 2][ar] = av.z; As[ak + 3][ar] = av.w;
        Bs[ak + 0][ar] = bv.x; Bs[ak + 1][ar] = bv.y;
        Bs[ak + 2][ar] = bv.z; Bs[ak + 3][ar] = bv.w;
        __syncthreads();
        #pragma unroll
        for (int kk = 0; kk < 16; kk++) {
            float4 a  = *(const float4*)&As[kk][ty * 4];
            float4 bb = *(const float4*)&Bs[kk][tx * 4];
            float ai[4] = {a.x, a.y, a.z, a.w};
            float bj[4] = {bb.x, bb.y, bb.z, bb.w};
            #pragma unroll
            for (int i = 0; i < 4; i++)
                #pragma unroll
                for (int j = 0; j < 4; j++)
                    acc[i][j] = fmaf(ai[i], bj[j], acc[i][j]);
        }
    }
    float4 bias = *(const float4*)&bo[n0 + tx * 4];
    #pragma unroll
    for (int i = 0; i < 4; i++) {
        float4 r = make_float4(acc[i][0] + bias.x, acc[i][1] + bias.y,
                               acc[i][2] + bias.z, acc[i][3] + bias.w);
        *(float4*)&out[(size_t)(m0 + ty * 4 + i) * C_ + n0 + tx * 4] = r;
    }
}

// ---------------------------------------------------------------------------
extern "C" void kernel_launch(void* const* d_in, const int* in_sizes, int n_in,
                              void* d_out, int out_size)
{
    const float* x  = (const float*)d_in[0];
    const float* Wq = (const float*)d_in[1];
    const float* Wk = (const float*)d_in[2];
    const float* Wv = (const float*)d_in[3];
    const float* Wo = (const float*)d_in[4];
    const float* bo = (const float*)d_in[5];
    float* out = (float*)d_out;

    dim3 g1((B_ * T_) / 64, 1, 3 * H_);          // 128 x 1 x 48
    qkv_gemm_kernel<<<g1, 256>>>(x, Wq, Wk, Wv);

    dim3 g2(T_ / 128, B_ * H_);                  // 16 x 64
    attn_kernel<<<g2, 128>>>();

    dim3 g3((B_ * T_) / 64, C_ / 64);            // 128 x 16
    proj_gemm_kernel<<<g3, 256>>>(Wo, bo, out);
}

// round 3
// speedup vs baseline: 1.3813x; 1.3813x over previous
#include <cuda_runtime.h>
#include <cuda_bf16.h>
#include <cstdint>

#define B_  4
#define T_  2048
#define C_  1024
#define H_  16
#define HS_ 64

// ---------------------------------------------------------------------------
// Scratch (allocation-free rule: __device__ globals)
// ---------------------------------------------------------------------------
__device__ float g_q[B_ * H_ * T_ * HS_];
__device__ float g_k[B_ * H_ * T_ * HS_];
__device__ float g_v[B_ * H_ * T_ * HS_];
__device__ float g_att[B_ * T_ * C_];

__device__ __nv_bfloat16 g_xhi[B_ * T_ * C_];
__device__ __nv_bfloat16 g_xlo[B_ * T_ * C_];
__device__ __nv_bfloat16 g_wthi[3 * H_ * HS_ * C_];   // [z=p*16+h][d][c]
__device__ __nv_bfloat16 g_wtlo[3 * H_ * HS_ * C_];
__device__ __nv_bfloat16 g_wohi[C_ * C_];             // [n][k]
__device__ __nv_bfloat16 g_wolo[C_ * C_];
__device__ __nv_bfloat16 g_ahi[B_ * T_ * C_];
__device__ __nv_bfloat16 g_alo[B_ * T_ * C_];

// ---------------------------------------------------------------------------
// Portable tensor-core primitives (sm_80+ ISA; compiles at base compute_103)
// ---------------------------------------------------------------------------
__device__ __forceinline__ uint32_t smem_u32(const void* p) {
    uint32_t a;
    asm("{ .reg .u64 t; cvta.to.shared.u64 t, %1; cvt.u32.u64 %0, t; }"
        : "=r"(a) : "l"(p));
    return a;
}

__device__ __forceinline__ void ldsm4(uint32_t* r, uint32_t addr) {
    asm volatile("ldmatrix.sync.aligned.m8n8.x4.shared.b16 {%0,%1,%2,%3}, [%4];"
        : "=r"(r[0]), "=r"(r[1]), "=r"(r[2]), "=r"(r[3]) : "r"(addr));
}

__device__ __forceinline__ void mma16816(float* c, const uint32_t* a,
                                         const uint32_t b0, const uint32_t b1) {
    asm volatile(
        "mma.sync.aligned.m16n8k16.row.col.f32.bf16.bf16.f32 "
        "{%0,%1,%2,%3}, {%4,%5,%6,%7}, {%8,%9}, {%0,%1,%2,%3};"
        : "+f"(c[0]), "+f"(c[1]), "+f"(c[2]), "+f"(c[3])
        : "r"(a[0]), "r"(a[1]), "r"(a[2]), "r"(a[3]), "r"(b0), "r"(b1));
}

// ---------------------------------------------------------------------------
// fp32 -> bf16 hi/lo split kernels
// ---------------------------------------------------------------------------
struct __align__(8) bf4 { __nv_bfloat16 a, b, c, d; };

__device__ __forceinline__ void split4(float4 v, bf4& hv, bf4& lv) {
    __nv_bfloat16 h0 = __float2bfloat16(v.x);
    __nv_bfloat16 h1 = __float2bfloat16(v.y);
    __nv_bfloat16 h2 = __float2bfloat16(v.z);
    __nv_bfloat16 h3 = __float2bfloat16(v.w);
    hv = {h0, h1, h2, h3};
    lv = {__float2bfloat16(v.x - __bfloat162float(h0)),
          __float2bfloat16(v.y - __bfloat162float(h1)),
          __float2bfloat16(v.z - __bfloat162float(h2)),
          __float2bfloat16(v.w - __bfloat162float(h3))};
}

__global__ __launch_bounds__(256) void split_kernel(
    const float* __restrict__ in,
    __nv_bfloat16* __restrict__ hi,
    __nv_bfloat16* __restrict__ lo, int n4)
{
    int i = blockIdx.x * blockDim.x + threadIdx.x;
    if (i >= n4) return;
    bf4 hv, lv;
    split4(((const float4*)in)[i], hv, lv);
    ((bf4*)hi)[i] = hv;
    ((bf4*)lo)[i] = lv;
}

__global__ __launch_bounds__(256) void split_att_kernel()
{
    int i = blockIdx.x * blockDim.x + threadIdx.x;
    bf4 hv, lv;
    split4(((const float4*)g_att)[i], hv, lv);
    ((bf4*)g_ahi)[i] = hv;
    ((bf4*)g_alo)[i] = lv;
}

// W[h][c][d] (fp32) -> Wt[z][d][c] (bf16 hi/lo), z = p*16+h
__global__ __launch_bounds__(256) void split_wqkv_kernel(
    const float* __restrict__ Wq,
    const float* __restrict__ Wk,
    const float* __restrict__ Wv)
{
    int z = blockIdx.y;
    int p = z >> 4, h = z & 15;
    const float* W = (p == 0 ? Wq : (p == 1 ? Wk : Wv)) + (size_t)h * C_ * HS_;
    int idx = blockIdx.x * blockDim.x + threadIdx.x;
    int d = idx & 63;
    int c = idx >> 6;
    float v = W[(size_t)c * HS_ + d];
    __nv_bfloat16 hv = __float2bfloat16(v);
    __nv_bfloat16 lv = __float2bfloat16(v - __bfloat162float(hv));
    size_t o = ((size_t)z * HS_ + d) * C_ + c;
    g_wthi[o] = hv;
    g_wtlo[o] = lv;
}

// ---------------------------------------------------------------------------
// HMMA GEMM mainloop: CTA tile 128(M) x 64(N), K = 1024 in BK=32 chunks.
// A,B both K-contiguous bf16 (hi/lo). Smem row stride 80B (conflict-free
// ldmatrix: 5 coprime 8). Warp grid 4x2, warp tile 32x32.
// acc[mt][nt][4]: mt 2 x m16, nt 4 x n8.
// ---------------------------------------------------------------------------
#define SA_ (128 * 80)
#define SB_ (64 * 80)

__device__ __forceinline__ void hmma_mainloop_128x64(
    const __nv_bfloat16* __restrict__ Ahi, const __nv_bfloat16* __restrict__ Alo,
    const __nv_bfloat16* __restrict__ Bhi, const __nv_bfloat16* __restrict__ Blo,
    int a_row0, int b_row0, unsigned char* smem, float acc[2][4][4])
{
    const int t    = threadIdx.x;
    const int wid  = t >> 5, lane = t & 31;
    const int warp_m = wid >> 1, warp_n = wid & 1;
    const int g = lane >> 3, lr = lane & 7;

    unsigned char* sAh = smem;
    unsigned char* sAl = smem + SA_;
    unsigned char* sBh = smem + 2 * SA_;
    unsigned char* sBl = smem + 2 * SA_ + SB_;
    const uint32_t uAh = smem_u32(sAh), uAl = smem_u32(sAl);
    const uint32_t uBh = smem_u32(sBh), uBl = smem_u32(sBl);

    // copy roles
    const int arow = t >> 1, asec = (t & 1) * 2;   // 2x uint4 per thread per buf
    const int brow = t >> 2, bsec = t & 3;         // 1x uint4

    // ldmatrix lane-address offsets (bytes), kk added per step
    uint32_t aoff[2], boff[2];
    #pragma unroll
    for (int mt = 0; mt < 2; mt++)
        aoff[mt] = (uint32_t)(warp_m * 32 + mt * 16 + (g & 1) * 8 + lr) * 80
                 + (uint32_t)((g >> 1) * 8) * 2;
    #pragma unroll
    for (int np = 0; np < 2; np++)
        boff[np] = (uint32_t)(warp_n * 32 + np * 16 + (g >> 1) * 8 + lr) * 80
                 + (uint32_t)((g & 1) * 8) * 2;

    #pragma unroll
    for (int mt = 0; mt < 2; mt++)
        #pragma unroll
        for (int nt = 0; nt < 4; nt++)
            #pragma unroll
            for (int i = 0; i < 4; i++) acc[mt][nt][i] = 0.f;

    for (int k0 = 0; k0 < C_; k0 += 32) {
        // global loads (hide behind previous iter's MMA via occupancy)
        const uint4* pAh = (const uint4*)(Ahi + (size_t)(a_row0 + arow) * C_ + k0 + asec * 8);
        const uint4* pAl = (const uint4*)(Alo + (size_t)(a_row0 + arow) * C_ + k0 + asec * 8);
        const uint4* pBh = (const uint4*)(Bhi + (size_t)(b_row0 + brow) * C_ + k0 + bsec * 8);
        const uint4* pBl = (const uint4*)(Blo + (size_t)(b_row0 + brow) * C_ + k0 + bsec * 8);
        uint4 vah0 = pAh[0], vah1 = pAh[1];
        uint4 val0 = pAl[0], val1 = pAl[1];
        uint4 vbh = pBh[0],  vbl = pBl[0];

        __syncthreads();
        *(uint4*)(sAh + arow * 80 + asec * 16)      = vah0;
        *(uint4*)(sAh + arow * 80 + asec * 16 + 16) = vah1;
        *(uint4*)(sAl + arow * 80 + asec * 16)      = val0;
        *(uint4*)(sAl + arow * 80 + asec * 16 + 16) = val1;
        *(uint4*)(sBh + brow * 80 + bsec * 16) = vbh;
        *(uint4*)(sBl + brow * 80 + bsec * 16) = vbl;
        __syncthreads();

        #pragma unroll
        for (int kk = 0; kk < 2; kk++) {
            const uint32_t kb = (uint32_t)kk * 32;   // 16 bf16 = 32 bytes
            uint32_t ah[2][4], al[2][4], bh[2][4], bl[2][4];
            #pragma unroll
            for (int mt = 0; mt < 2; mt++) {
                ldsm4(ah[mt], uAh + aoff[mt] + kb);
                ldsm4(al[mt], uAl + aoff[mt] + kb);
            }
            #pragma unroll
            for (int np = 0; np < 2; np++) {
                ldsm4(bh[np], uBh + boff[np] + kb);
                ldsm4(bl[np], uBl + boff[np] + kb);
            }
            #pragma unroll
            for (int mt = 0; mt < 2; mt++)
                #pragma unroll
                for (int np = 0; np < 2; np++)
                    #pragma unroll
                    for (int hf = 0; hf < 2; hf++) {
                        const int nt = np * 2 + hf;
                        mma16816(acc[mt][nt], ah[mt], bh[np][hf * 2], bh[np][hf * 2 + 1]);
                        mma16816(acc[mt][nt], ah[mt], bl[np][hf * 2], bl[np][hf * 2 + 1]);
                        mma16816(acc[mt][nt], al[mt], bh[np][hf * 2], bh[np][hf * 2 + 1]);
                    }
        }
    }
}

// QKV: grid (64 m-tiles, 48 z), block 256
__global__ __launch_bounds__(256, 2) void qkv_mma_kernel()
{
    __shared__ __align__(16) unsigned char smem[2 * SA_ + 2 * SB_];
    const int m0 = blockIdx.x * 128;
    const int z = blockIdx.y;
    const int p = z >> 4, h = z & 15;

    float acc[2][4][4];
    hmma_mainloop_128x64(g_xhi, g_xlo, g_wthi, g_wtlo,
                         m0, z * HS_, smem, acc);

    float* outb = (p == 0 ? g_q : (p == 1 ? g_k : g_v));
    const int wid = threadIdx.x >> 5, lane = threadIdx.x & 31;
    const int warp_m = wid >> 1, warp_n = wid & 1;
    const int qrow = lane >> 2, qcol = (lane & 3) * 2;

    #pragma unroll
    for (int mt = 0; mt < 2; mt++)
        #pragma unroll
        for (int nt = 0; nt < 4; nt++) {
            const int d = warp_n * 32 + nt * 8 + qcol;
            #pragma unroll
            for (int rh = 0; rh < 2; rh++) {
                const int gm = m0 + warp_m * 32 + mt * 16 + qrow + rh * 8;
                const int b = gm >> 11, tt = gm & (T_ - 1);
                float* op = outb + ((size_t)(b * H_ + h) * T_ + tt) * HS_ + d;
                *(float2*)op = make_float2(acc[mt][nt][rh * 2], acc[mt][nt][rh * 2 + 1]);
            }
        }
}

// Output projection: grid (64 m-tiles, 16 n-tiles), block 256
__global__ __launch_bounds__(256, 2) void proj_mma_kernel(
    const float* __restrict__ bo, float* __restrict__ out)
{
    __shared__ __align__(16) unsigned char smem[2 * SA_ + 2 * SB_];
    const int m0 = blockIdx.x * 128;
    const int n0 = blockIdx.y * 64;

    float acc[2][4][4];
    hmma_mainloop_128x64(g_ahi, g_alo, g_wohi, g_wolo,
                         m0, n0, smem, acc);

    const int wid = threadIdx.x >> 5, lane = threadIdx.x & 31;
    const int warp_m = wid >> 1, warp_n = wid & 1;
    const int qrow = lane >> 2, qcol = (lane & 3) * 2;

    #pragma unroll
    for (int mt = 0; mt < 2; mt++)
        #pragma unroll
        for (int nt = 0; nt < 4; nt++) {
            const int n = n0 + warp_n * 32 + nt * 8 + qcol;
            const float2 bb = *(const float2*)&bo[n];
            #pragma unroll
            for (int rh = 0; rh < 2; rh++) {
                const int gm = m0 + warp_m * 32 + mt * 16 + qrow + rh * 8;
                *(float2*)(out + (size_t)gm * C_ + n) =
                    make_float2(acc[mt][nt][rh * 2] + bb.x,
                                acc[mt][nt][rh * 2 + 1] + bb.y);
            }
        }
}

// ---------------------------------------------------------------------------
// Causal flash attention, fp32 scalar (unchanged from R1; tensorize next)
// ---------------------------------------------------------------------------
__global__ __launch_bounds__(128) void attn_kernel()
{
    const int bh  = blockIdx.y;
    const int r0  = blockIdx.x * 128;
    const int tid = threadIdx.x;
    const int row = r0 + tid;

    const float* Q = g_q + (size_t)bh * T_ * HS_;
    const float* K = g_k + (size_t)bh * T_ * HS_;
    const float* V = g_v + (size_t)bh * T_ * HS_;

    __shared__ float Ks[64 * 64];
    __shared__ float Vs[64 * 64];

    float q[64];
    #pragma unroll
    for (int d = 0; d < 64; d += 4) {
        float4 t = *(const float4*)&Q[(size_t)row * HS_ + d];
        q[d] = t.x; q[d + 1] = t.y; q[d + 2] = t.z; q[d + 3] = t.w;
    }
    float o[64];
    #pragma unroll
    for (int d = 0; d < 64; d++) o[d] = 0.f;
    float m = -1e30f, l = 0.f;
    const float scale = 0.125f;

    const int kv_end = r0 + 128;
    for (int j0 = 0; j0 < kv_end; j0 += 64) {
        __syncthreads();
        const float4* Kg = (const float4*)&K[(size_t)j0 * HS_];
        const float4* Vg = (const float4*)&V[(size_t)j0 * HS_];
        #pragma unroll
        for (int i = 0; i < 8; i++) {
            ((float4*)Ks)[tid + i * 128] = Kg[tid + i * 128];
            ((float4*)Vs)[tid + i * 128] = Vg[tid + i * 128];
        }
        __syncthreads();

        #pragma unroll 1
        for (int jc = 0; jc < 64; jc += 8) {
            float s[8];
            #pragma unroll
            for (int jj = 0; jj < 8; jj++) {
                const float4* kr4 = (const float4*)&Ks[(jc + jj) * 64];
                float s0 = 0.f, s1 = 0.f, s2 = 0.f, s3 = 0.f;
                #pragma unroll
                for (int d4 = 0; d4 < 16; d4++) {
                    float4 kv = kr4[d4];
                    s0 = fmaf(q[d4 * 4 + 0], kv.x, s0);
                    s1 = fmaf(q[d4 * 4 + 1], kv.y, s1);
                    s2 = fmaf(q[d4 * 4 + 2], kv.z, s2);
                    s3 = fmaf(q[d4 * 4 + 3], kv.w, s3);
                }
                float sv = ((s0 + s1) + (s2 + s3)) * scale;
                if (j0 + jc + jj > row) sv = -1e30f;
                s[jj] = sv;
            }
            float mc = s[0];
            #pragma unroll
            for (int jj = 1; jj < 8; jj++) mc = fmaxf(mc, s[jj]);
            float m_new = fmaxf(m, mc);
            if (m_new < -1e29f) continue;
            float corr = __expf(m - m_new);
            m = m_new;
            float p[8];
            float ps = 0.f;
            #pragma unroll
            for (int jj = 0; jj < 8; jj++) {
                p[jj] = __expf(s[jj] - m);
                ps += p[jj];
            }
            l = l * corr + ps;
            #pragma unroll
            for (int d = 0; d < 64; d++) o[d] *= corr;
            #pragma unroll
            for (int jj = 0; jj < 8; jj++) {
                const float4* vr4 = (const float4*)&Vs[(jc + jj) * 64];
                float pj = p[jj];
                #pragma unroll
                for (int d4 = 0; d4 < 16; d4++) {
                    float4 vv = vr4[d4];
                    o[d4 * 4 + 0] = fmaf(pj, vv.x, o[d4 * 4 + 0]);
                    o[d4 * 4 + 1] = fmaf(pj, vv.y, o[d4 * 4 + 1]);
                    o[d4 * 4 + 2] = fmaf(pj, vv.z, o[d4 * 4 + 2]);
                    o[d4 * 4 + 3] = fmaf(pj, vv.w, o[d4 * 4 + 3]);
                }
            }
        }
    }
    const float inv_l = 1.f / l;
    const int b = bh >> 4, h = bh & 15;
    float* outp = g_att + ((size_t)(b * T_ + row)) * C_ + h * HS_;
    #pragma unroll
    for (int d = 0; d < 64; d += 4) {
        float4 r = make_float4(o[d] * inv_l, o[d + 1] * inv_l,
                               o[d + 2] * inv_l, o[d + 3] * inv_l);
        *(float4*)&outp[d] = r;
    }
}

// ---------------------------------------------------------------------------
extern "C" void kernel_launch(void* const* d_in, const int* in_sizes, int n_in,
                              void* d_out, int out_size)
{
    const float* x  = (const float*)d_in[0];
    const float* Wq = (const float*)d_in[1];
    const float* Wk = (const float*)d_in[2];
    const float* Wv = (const float*)d_in[3];
    const float* Wo = (const float*)d_in[4];
    const float* bo = (const float*)d_in[5];
    float* out = (float*)d_out;

    __nv_bfloat16 *xhi, *xlo, *wohi, *wolo;
    cudaGetSymbolAddress((void**)&xhi,  g_xhi);
    cudaGetSymbolAddress((void**)&xlo,  g_xlo);
    cudaGetSymbolAddress((void**)&wohi, g_wohi);
    cudaGetSymbolAddress((void**)&wolo, g_wolo);

    split_kernel<<<(B_ * T_ * C_ / 4 + 255) / 256, 256>>>(x, xhi, xlo, B_ * T_ * C_ / 4);
    split_wqkv_kernel<<<dim3(HS_ * C_ / 256, 48), 256>>>(Wq, Wk, Wv);
    split_kernel<<<(C_ * C_ / 4 + 255) / 256, 256>>>(Wo, wohi, wolo, C_ * C_ / 4);

    qkv_mma_kernel<<<dim3(B_ * T_ / 128, 48), 256>>>();

    attn_kernel<<<dim3(T_ / 128, B_ * H_), 128>>>();

    split_att_kernel<<<B_ * T_ * C_ / 4 / 256, 256>>>();

    proj_mma_kernel<<<dim3(B_ * T_ / 128, C_ / 64), 256>>>(bo, out);
}

// round 6
// speedup vs baseline: 2.3786x; 1.7220x over previous
#include <cuda_runtime.h>
#include <cuda_bf16.h>
#include <cstdint>

#define B_  4
#define T_  2048
#define C_  1024
#define H_  16
#define HS_ 64

// ---------------------------------------------------------------------------
// Scratch (allocation-free rule: __device__ globals)
// ---------------------------------------------------------------------------
__device__ __nv_bfloat16 g_xhi[B_ * T_ * C_];
__device__ __nv_bfloat16 g_xlo[B_ * T_ * C_];
__device__ __nv_bfloat16 g_wthi[3 * H_ * HS_ * C_];   // [z=p*16+h][d][c]
__device__ __nv_bfloat16 g_wtlo[3 * H_ * HS_ * C_];
__device__ __nv_bfloat16 g_wohi[C_ * C_];             // [n][k]
__device__ __nv_bfloat16 g_wolo[C_ * C_];
__device__ __nv_bfloat16 g_ahi[B_ * T_ * C_];
__device__ __nv_bfloat16 g_alo[B_ * T_ * C_];

// q/k/v in bf16 hi/lo, layout [bh][t][64]; q pre-scaled by 1/sqrt(HS)
__device__ __nv_bfloat16 g_qh[B_ * H_ * T_ * HS_];
__device__ __nv_bfloat16 g_ql[B_ * H_ * T_ * HS_];
__device__ __nv_bfloat16 g_kh[B_ * H_ * T_ * HS_];
__device__ __nv_bfloat16 g_kl[B_ * H_ * T_ * HS_];
__device__ __nv_bfloat16 g_vh[B_ * H_ * T_ * HS_];
__device__ __nv_bfloat16 g_vl[B_ * H_ * T_ * HS_];

// ---------------------------------------------------------------------------
// Portable tensor-core primitives (sm_80+ ISA; compiles at base compute_103)
// ---------------------------------------------------------------------------
__device__ __forceinline__ uint32_t smem_u32(const void* p) {
    uint32_t a;
    asm("{ .reg .u64 t; cvta.to.shared.u64 t, %1; cvt.u32.u64 %0, t; }"
        : "=r"(a) : "l"(p));
    return a;
}

__device__ __forceinline__ void ldsm4(uint32_t* r, uint32_t addr) {
    asm volatile("ldmatrix.sync.aligned.m8n8.x4.shared.b16 {%0,%1,%2,%3}, [%4];"
        : "=r"(r[0]), "=r"(r[1]), "=r"(r[2]), "=r"(r[3]) : "r"(addr));
}

__device__ __forceinline__ void ldsm4t(uint32_t* r, uint32_t addr) {
    asm volatile("ldmatrix.sync.aligned.m8n8.x4.trans.shared.b16 {%0,%1,%2,%3}, [%4];"
        : "=r"(r[0]), "=r"(r[1]), "=r"(r[2]), "=r"(r[3]) : "r"(addr));
}

__device__ __forceinline__ void mma16816(float* c, const uint32_t* a,
                                         const uint32_t b0, const uint32_t b1) {
    asm volatile(
        "mma.sync.aligned.m16n8k16.row.col.f32.bf16.bf16.f32 "
        "{%0,%1,%2,%3}, {%4,%5,%6,%7}, {%8,%9}, {%0,%1,%2,%3};"
        : "+f"(c[0]), "+f"(c[1]), "+f"(c[2]), "+f"(c[3])
        : "r"(a[0]), "r"(a[1]), "r"(a[2]), "r"(a[3]), "r"(b0), "r"(b1));
}

__device__ __forceinline__ uint32_t packbf(float a, float b) {
    __nv_bfloat162 t = __floats2bfloat162_rn(a, b);
    return *(uint32_t*)&t;
}

// ---------------------------------------------------------------------------
// fp32 -> bf16 hi/lo split kernels
// ---------------------------------------------------------------------------
struct __align__(8) bf4 { __nv_bfloat16 a, b, c, d; };

__device__ __forceinline__ void split4(float4 v, bf4& hv, bf4& lv) {
    __nv_bfloat16 h0 = __float2bfloat16(v.x);
    __nv_bfloat16 h1 = __float2bfloat16(v.y);
    __nv_bfloat16 h2 = __float2bfloat16(v.z);
    __nv_bfloat16 h3 = __float2bfloat16(v.w);
    hv = {h0, h1, h2, h3};
    lv = {__float2bfloat16(v.x - __bfloat162float(h0)),
          __float2bfloat16(v.y - __bfloat162float(h1)),
          __float2bfloat16(v.z - __bfloat162float(h2)),
          __float2bfloat16(v.w - __bfloat162float(h3))};
}

__global__ __launch_bounds__(256) void split_kernel(
    const float* __restrict__ in,
    __nv_bfloat16* __restrict__ hi,
    __nv_bfloat16* __restrict__ lo, int n4)
{
    int i = blockIdx.x * blockDim.x + threadIdx.x;
    if (i >= n4) return;
    bf4 hv, lv;
    split4(((const float4*)in)[i], hv, lv);
    ((bf4*)hi)[i] = hv;
    ((bf4*)lo)[i] = lv;
}

// W[h][c][d] (fp32) -> Wt[z][d][c] (bf16 hi/lo), z = p*16+h
__global__ __launch_bounds__(256) void split_wqkv_kernel(
    const float* __restrict__ Wq,
    const float* __restrict__ Wk,
    const float* __restrict__ Wv)
{
    int z = blockIdx.y;
    int p = z >> 4, h = z & 15;
    const float* W = (p == 0 ? Wq : (p == 1 ? Wk : Wv)) + (size_t)h * C_ * HS_;
    int idx = blockIdx.x * blockDim.x + threadIdx.x;
    int d = idx & 63;
    int c = idx >> 6;
    float v = W[(size_t)c * HS_ + d];
    __nv_bfloat16 hv = __float2bfloat16(v);
    __nv_bfloat16 lv = __float2bfloat16(v - __bfloat162float(hv));
    size_t o = ((size_t)z * HS_ + d) * C_ + c;
    g_wthi[o] = hv;
    g_wtlo[o] = lv;
}

// ---------------------------------------------------------------------------
// HMMA GEMM mainloop: CTA tile 128(M) x 64(N), K = 1024 in BK=32 chunks.
// ---------------------------------------------------------------------------
#define SA_ (128 * 80)
#define SB_ (64 * 80)

__device__ __forceinline__ void hmma_mainloop_128x64(
    const __nv_bfloat16* __restrict__ Ahi, const __nv_bfloat16* __restrict__ Alo,
    const __nv_bfloat16* __restrict__ Bhi, const __nv_bfloat16* __restrict__ Blo,
    int a_row0, int b_row0, unsigned char* smem, float acc[2][4][4])
{
    const int t    = threadIdx.x;
    const int wid  = t >> 5, lane = t & 31;
    const int warp_m = wid >> 1, warp_n = wid & 1;
    const int g = lane >> 3, lr = lane & 7;

    unsigned char* sAh = smem;
    unsigned char* sAl = smem + SA_;
    unsigned char* sBh = smem + 2 * SA_;
    unsigned char* sBl = smem + 2 * SA_ + SB_;
    const uint32_t uAh = smem_u32(sAh), uAl = smem_u32(sAl);
    const uint32_t uBh = smem_u32(sBh), uBl = smem_u32(sBl);

    const int arow = t >> 1, asec = (t & 1) * 2;
    const int brow = t >> 2, bsec = t & 3;

    uint32_t aoff[2], boff[2];
    #pragma unroll
    for (int mt = 0; mt < 2; mt++)
        aoff[mt] = (uint32_t)(warp_m * 32 + mt * 16 + (g & 1) * 8 + lr) * 80
                 + (uint32_t)((g >> 1) * 8) * 2;
    #pragma unroll
    for (int np = 0; np < 2; np++)
        boff[np] = (uint32_t)(warp_n * 32 + np * 16 + (g >> 1) * 8 + lr) * 80
                 + (uint32_t)((g & 1) * 8) * 2;

    #pragma unroll
    for (int mt = 0; mt < 2; mt++)
        #pragma unroll
        for (int nt = 0; nt < 4; nt++)
            #pragma unroll
            for (int i = 0; i < 4; i++) acc[mt][nt][i] = 0.f;

    for (int k0 = 0; k0 < C_; k0 += 32) {
        const uint4* pAh = (const uint4*)(Ahi + (size_t)(a_row0 + arow) * C_ + k0 + asec * 8);
        const uint4* pAl = (const uint4*)(Alo + (size_t)(a_row0 + arow) * C_ + k0 + asec * 8);
        const uint4* pBh = (const uint4*)(Bhi + (size_t)(b_row0 + brow) * C_ + k0 + bsec * 8);
        const uint4* pBl = (const uint4*)(Blo + (size_t)(b_row0 + brow) * C_ + k0 + bsec * 8);
        uint4 vah0 = pAh[0], vah1 = pAh[1];
        uint4 val0 = pAl[0], val1 = pAl[1];
        uint4 vbh = pBh[0],  vbl = pBl[0];

        __syncthreads();
        *(uint4*)(sAh + arow * 80 + asec * 16)      = vah0;
        *(uint4*)(sAh + arow * 80 + asec * 16 + 16) = vah1;
        *(uint4*)(sAl + arow * 80 + asec * 16)      = val0;
        *(uint4*)(sAl + arow * 80 + asec * 16 + 16) = val1;
        *(uint4*)(sBh + brow * 80 + bsec * 16) = vbh;
        *(uint4*)(sBl + brow * 80 + bsec * 16) = vbl;
        __syncthreads();

        #pragma unroll
        for (int kk = 0; kk < 2; kk++) {
            const uint32_t kb = (uint32_t)kk * 32;
            uint32_t ah[2][4], al[2][4], bh[2][4], bl[2][4];
            #pragma unroll
            for (int mt = 0; mt < 2; mt++) {
                ldsm4(ah[mt], uAh + aoff[mt] + kb);
                ldsm4(al[mt], uAl + aoff[mt] + kb);
            }
            #pragma unroll
            for (int np = 0; np < 2; np++) {
                ldsm4(bh[np], uBh + boff[np] + kb);
                ldsm4(bl[np], uBl + boff[np] + kb);
            }
            #pragma unroll
            for (int mt = 0; mt < 2; mt++)
                #pragma unroll
                for (int np = 0; np < 2; np++)
                    #pragma unroll
                    for (int hf = 0; hf < 2; hf++) {
                        const int nt = np * 2 + hf;
                        mma16816(acc[mt][nt], ah[mt], bh[np][hf * 2], bh[np][hf * 2 + 1]);
                        mma16816(acc[mt][nt], ah[mt], bl[np][hf * 2], bl[np][hf * 2 + 1]);
                        mma16816(acc[mt][nt], al[mt], bh[np][hf * 2], bh[np][hf * 2 + 1]);
                    }
        }
    }
}

// QKV: grid (64 m-tiles, 48 z), block 256. Epilogue writes bf16 hi/lo (q scaled).
__global__ __launch_bounds__(256, 2) void qkv_mma_kernel()
{
    __shared__ __align__(16) unsigned char smem[2 * SA_ + 2 * SB_];
    const int m0 = blockIdx.x * 128;
    const int z = blockIdx.y;
    const int p = z >> 4, h = z & 15;

    float acc[2][4][4];
    hmma_mainloop_128x64(g_xhi, g_xlo, g_wthi, g_wtlo,
                         m0, z * HS_, smem, acc);

    __nv_bfloat16* outh = (p == 0 ? g_qh : (p == 1 ? g_kh : g_vh));
    __nv_bfloat16* outl = (p == 0 ? g_ql : (p == 1 ? g_kl : g_vl));
    const float scale = (p == 0) ? 0.125f : 1.0f;

    const int wid = threadIdx.x >> 5, lane = threadIdx.x & 31;
    const int warp_m = wid >> 1, warp_n = wid & 1;
    const int qrow = lane >> 2, qcol = (lane & 3) * 2;

    #pragma unroll
    for (int mt = 0; mt < 2; mt++)
        #pragma unroll
        for (int nt = 0; nt < 4; nt++) {
            const int d = warp_n * 32 + nt * 8 + qcol;
            #pragma unroll
            for (int rh = 0; rh < 2; rh++) {
                const int gm = m0 + warp_m * 32 + mt * 16 + qrow + rh * 8;
                const int b = gm >> 11, tt = gm & (T_ - 1);
                const size_t idx = ((size_t)(b * H_ + h) * T_ + tt) * HS_ + d;
                float v0 = acc[mt][nt][rh * 2] * scale;
                float v1 = acc[mt][nt][rh * 2 + 1] * scale;
                float h0 = __bfloat162float(__float2bfloat16(v0));
                float h1 = __bfloat162float(__float2bfloat16(v1));
                *(uint32_t*)&outh[idx] = packbf(h0, h1);
                *(uint32_t*)&outl[idx] = packbf(v0 - h0, v1 - h1);
            }
        }
}

// Output projection: grid (64 m-tiles, 16 n-tiles), block 256
__global__ __launch_bounds__(256, 2) void proj_mma_kernel(
    const float* __restrict__ bo, float* __restrict__ out)
{
    __shared__ __align__(16) unsigned char smem[2 * SA_ + 2 * SB_];
    const int m0 = blockIdx.x * 128;
    const int n0 = blockIdx.y * 64;

    float acc[2][4][4];
    hmma_mainloop_128x64(g_ahi, g_alo, g_wohi, g_wolo,
                         m0, n0, smem, acc);

    const int wid = threadIdx.x >> 5, lane = threadIdx.x & 31;
    const int warp_m = wid >> 1, warp_n = wid & 1;
    const int qrow = lane >> 2, qcol = (lane & 3) * 2;

    #pragma unroll
    for (int mt = 0; mt < 2; mt++)
        #pragma unroll
        for (int nt = 0; nt < 4; nt++) {
            const int n = n0 + warp_n * 32 + nt * 8 + qcol;
            const float2 bb = *(const float2*)&bo[n];
            #pragma unroll
            for (int rh = 0; rh < 2; rh++) {
                const int gm = m0 + warp_m * 32 + mt * 16 + qrow + rh * 8;
                *(float2*)(out + (size_t)gm * C_ + n) =
                    make_float2(acc[mt][nt][rh * 2] + bb.x,
                                acc[mt][nt][rh * 2 + 1] + bb.y);
            }
        }
}

// ---------------------------------------------------------------------------
// HMMA causal flash attention.
// CTA: 64 q-rows x one bh, 4 warps (warp w: rows w*16..w*16+16, FULL S rows).
// S = QK^T and O = PV both 3-term bf16 hi/lo. Smem row stride 144B.
// Row = 64 bf16 = 128 B; 2 threads/row, 64 B (4x uint4) per thread per buffer.
// ---------------------------------------------------------------------------
#define QSTR 144
#define SQ_  (64 * QSTR)   // per hi/lo Q buffer
#define SKV_ (64 * QSTR)   // per K/V buffer

__global__ __launch_bounds__(128) void attn_hmma_kernel()
{
    __shared__ __align__(16) unsigned char smem[2 * SQ_ + 4 * SKV_];
    unsigned char* sQh = smem;
    unsigned char* sQl = smem + SQ_;
    unsigned char* sKh = smem + 2 * SQ_;
    unsigned char* sKl = sKh + SKV_;
    unsigned char* sVh = sKl + SKV_;
    unsigned char* sVl = sVh + SKV_;
    const uint32_t uQh = smem_u32(sQh), uQl = smem_u32(sQl);
    const uint32_t uKh = smem_u32(sKh), uKl = smem_u32(sKl);
    const uint32_t uVh = smem_u32(sVh), uVl = smem_u32(sVl);

    const int bh = blockIdx.y;
    const int r0 = blockIdx.x * 64;
    const int t  = threadIdx.x;
    const int w  = t >> 5, lane = t & 31;
    const int g = lane >> 3, lr = lane & 7;
    const int qr = lane >> 2, qc = lane & 3;

    const size_t base = (size_t)bh * T_ * HS_;

    // copy roles: 2 threads per row, 64 bytes each
    const int crow = t >> 1;
    const int coff = (t & 1) * 64;    // byte offset within 128-byte row

    // ---- prologue: Q tile -> smem -> fragments
    {
        const unsigned char* gh =
            (const unsigned char*)(g_qh + base + (size_t)(r0 + crow) * HS_) + coff;
        const unsigned char* gl =
            (const unsigned char*)(g_ql + base + (size_t)(r0 + crow) * HS_) + coff;
        uint4 a0 = ((const uint4*)gh)[0], a1 = ((const uint4*)gh)[1];
        uint4 a2 = ((const uint4*)gh)[2], a3 = ((const uint4*)gh)[3];
        uint4 b0 = ((const uint4*)gl)[0], b1 = ((const uint4*)gl)[1];
        uint4 b2 = ((const uint4*)gl)[2], b3 = ((const uint4*)gl)[3];
        uint4* dh = (uint4*)(sQh + crow * QSTR + coff);
        uint4* dl = (uint4*)(sQl + crow * QSTR + coff);
        dh[0] = a0; dh[1] = a1; dh[2] = a2; dh[3] = a3;
        dl[0] = b0; dl[1] = b1; dl[2] = b2; dl[3] = b3;
    }
    __syncthreads();

    uint32_t qh[4][4], ql[4][4];
    {
        const uint32_t qoff = (uint32_t)(w * 16 + (g & 1) * 8 + lr) * QSTR
                            + (uint32_t)((g >> 1) * 8) * 2;
        #pragma unroll
        for (int ks = 0; ks < 4; ks++) {
            ldsm4(qh[ks], uQh + qoff + ks * 32);
            ldsm4(ql[ks], uQl + qoff + ks * 32);
        }
    }

    // ---- state
    float accO[8][4];
    #pragma unroll
    for (int nt = 0; nt < 8; nt++)
        #pragma unroll
        for (int i = 0; i < 4; i++) accO[nt][i] = 0.f;
    float mrow[2] = {-1e30f, -1e30f};
    float lrow[2] = {0.f, 0.f};

    // K-frag (non-trans) lane offsets: n-row groups
    uint32_t koff[4];
    #pragma unroll
    for (int np = 0; np < 4; np++)
        koff[np] = (uint32_t)(np * 16 + (g >> 1) * 8 + lr) * QSTR
                 + (uint32_t)((g & 1) * 8) * 2;
    // V-frag (trans): row = kv, col = d
    const uint32_t vrow = (uint32_t)((g & 1) * 8 + lr);
    const uint32_t vcol = (uint32_t)((g >> 1) * 8) * 2;

    // ---- main loop over kv tiles (causal: j0 <= r0)
    for (int j0 = 0; j0 <= r0; j0 += 64) {
        __syncthreads();
        {
            const unsigned char* pkh =
                (const unsigned char*)(g_kh + base + (size_t)(j0 + crow) * HS_) + coff;
            const unsigned char* pkl =
                (const unsigned char*)(g_kl + base + (size_t)(j0 + crow) * HS_) + coff;
            const unsigned char* pvh =
                (const unsigned char*)(g_vh + base + (size_t)(j0 + crow) * HS_) + coff;
            const unsigned char* pvl =
                (const unsigned char*)(g_vl + base + (size_t)(j0 + crow) * HS_) + coff;
            uint4 kh0 = ((const uint4*)pkh)[0], kh1 = ((const uint4*)pkh)[1];
            uint4 kh2 = ((const uint4*)pkh)[2], kh3 = ((const uint4*)pkh)[3];
            uint4 kl0 = ((const uint4*)pkl)[0], kl1 = ((const uint4*)pkl)[1];
            uint4 kl2 = ((const uint4*)pkl)[2], kl3 = ((const uint4*)pkl)[3];
            uint4 vh0 = ((const uint4*)pvh)[0], vh1 = ((const uint4*)pvh)[1];
            uint4 vh2 = ((const uint4*)pvh)[2], vh3 = ((const uint4*)pvh)[3];
            uint4 vl0 = ((const uint4*)pvl)[0], vl1 = ((const uint4*)pvl)[1];
            uint4 vl2 = ((const uint4*)pvl)[2], vl3 = ((const uint4*)pvl)[3];
            const uint32_t doff = crow * QSTR + coff;
            uint4* dkh = (uint4*)(sKh + doff);
            uint4* dkl = (uint4*)(sKl + doff);
            uint4* dvh = (uint4*)(sVh + doff);
            uint4* dvl = (uint4*)(sVl + doff);
            dkh[0] = kh0; dkh[1] = kh1; dkh[2] = kh2; dkh[3] = kh3;
            dkl[0] = kl0; dkl[1] = kl1; dkl[2] = kl2; dkl[3] = kl3;
            dvh[0] = vh0; dvh[1] = vh1; dvh[2] = vh2; dvh[3] = vh3;
            dvl[0] = vl0; dvl[1] = vl1; dvl[2] = vl2; dvl[3] = vl3;
        }
        __syncthreads();

        // ---- S = Q K^T (3-term)
        float accS[8][4];
        #pragma unroll
        for (int nt = 0; nt < 8; nt++)
            #pragma unroll
            for (int i = 0; i < 4; i++) accS[nt][i] = 0.f;

        #pragma unroll
        for (int ks = 0; ks < 4; ks++) {
            #pragma unroll
            for (int np = 0; np < 4; np++) {
                uint32_t kfh[4], kfl[4];
                ldsm4(kfh, uKh + koff[np] + ks * 32);
                ldsm4(kfl, uKl + koff[np] + ks * 32);
                #pragma unroll
                for (int hf = 0; hf < 2; hf++) {
                    const int nt = np * 2 + hf;
                    mma16816(accS[nt], qh[ks], kfh[hf * 2], kfh[hf * 2 + 1]);
                    mma16816(accS[nt], qh[ks], kfl[hf * 2], kfl[hf * 2 + 1]);
                    mma16816(accS[nt], ql[ks], kfh[hf * 2], kfh[hf * 2 + 1]);
                }
            }
        }

        // ---- causal mask on diagonal tile
        if (j0 == r0) {
            #pragma unroll
            for (int nt = 0; nt < 8; nt++)
                #pragma unroll
                for (int i = 0; i < 4; i++) {
                    const int col = nt * 8 + qc * 2 + (i & 1);
                    const int rr = w * 16 + qr + (i >> 1) * 8;
                    if (col > rr) accS[nt][i] = -1e30f;
                }
        }

        // ---- online softmax (rows fully within 4-lane group)
        float corr[2];
        #pragma unroll
        for (int hrow = 0; hrow < 2; hrow++) {
            float mx = -1e30f;
            #pragma unroll
            for (int nt = 0; nt < 8; nt++) {
                mx = fmaxf(mx, fmaxf(accS[nt][hrow * 2], accS[nt][hrow * 2 + 1]));
            }
            mx = fmaxf(mx, __shfl_xor_sync(0xffffffffu, mx, 1));
            mx = fmaxf(mx, __shfl_xor_sync(0xffffffffu, mx, 2));
            const float m_new = fmaxf(mrow[hrow], mx);
            corr[hrow] = __expf(mrow[hrow] - m_new);
            mrow[hrow] = m_new;
            float rs = 0.f;
            #pragma unroll
            for (int nt = 0; nt < 8; nt++) {
                float p0 = __expf(accS[nt][hrow * 2]     - m_new);
                float p1 = __expf(accS[nt][hrow * 2 + 1] - m_new);
                accS[nt][hrow * 2]     = p0;
                accS[nt][hrow * 2 + 1] = p1;
                rs += p0 + p1;
            }
            rs += __shfl_xor_sync(0xffffffffu, rs, 1);
            rs += __shfl_xor_sync(0xffffffffu, rs, 2);
            lrow[hrow] = lrow[hrow] * corr[hrow] + rs;
        }
        #pragma unroll
        for (int nt = 0; nt < 8; nt++) {
            accO[nt][0] *= corr[0]; accO[nt][1] *= corr[0];
            accO[nt][2] *= corr[1]; accO[nt][3] *= corr[1];
        }

        // ---- P fragments (hi/lo) and O += P V (3-term)
        #pragma unroll
        for (int ks = 0; ks < 4; ks++) {
            uint32_t pfh[4], pfl[4];
            #pragma unroll
            for (int half = 0; half < 2; half++) {
                const int nt = ks * 2 + half;
                #pragma unroll
                for (int rh = 0; rh < 2; rh++) {
                    float v0 = accS[nt][rh * 2], v1 = accS[nt][rh * 2 + 1];
                    float h0 = __bfloat162float(__float2bfloat16(v0));
                    float h1 = __bfloat162float(__float2bfloat16(v1));
                    pfh[half * 2 + rh] = packbf(h0, h1);
                    pfl[half * 2 + rh] = packbf(v0 - h0, v1 - h1);
                }
            }
            #pragma unroll
            for (int np = 0; np < 4; np++) {
                uint32_t vfh[4], vfl[4];
                const uint32_t va = (vrow + ks * 16) * QSTR + np * 32 + vcol;
                ldsm4t(vfh, uVh + va);
                ldsm4t(vfl, uVl + va);
                #pragma unroll
                for (int hf = 0; hf < 2; hf++) {
                    const int nt = np * 2 + hf;
                    mma16816(accO[nt], pfh, vfh[hf * 2], vfh[hf * 2 + 1]);
                    mma16816(accO[nt], pfh, vfl[hf * 2], vfl[hf * 2 + 1]);
                    mma16816(accO[nt], pfl, vfh[hf * 2], vfh[hf * 2 + 1]);
                }
            }
        }
    }

    // ---- epilogue: normalize, split to bf16 hi/lo, write proj input
    const float inv0 = 1.f / lrow[0];
    const float inv1 = 1.f / lrow[1];
    const int b = bh >> 4, hh = bh & 15;
    #pragma unroll
    for (int nt = 0; nt < 8; nt++) {
        const int d = hh * 64 + nt * 8 + qc * 2;
        #pragma unroll
        for (int rh = 0; rh < 2; rh++) {
            const float inv = rh ? inv1 : inv0;
            const int row = r0 + w * 16 + qr + rh * 8;
            const size_t idx = (size_t)(b * T_ + row) * C_ + d;
            float v0 = accO[nt][rh * 2] * inv;
            float v1 = accO[nt][rh * 2 + 1] * inv;
            float h0 = __bfloat162float(__float2bfloat16(v0));
            float h1 = __bfloat162float(__float2bfloat16(v1));
            *(uint32_t*)&g_ahi[idx] = packbf(h0, h1);
            *(uint32_t*)&g_alo[idx] = packbf(v0 - h0, v1 - h1);
        }
    }
}

// ---------------------------------------------------------------------------
extern "C" void kernel_launch(void* const* d_in, const int* in_sizes, int n_in,
                              void* d_out, int out_size)
{
    const float* x  = (const float*)d_in[0];
    const float* Wq = (const float*)d_in[1];
    const float* Wk = (const float*)d_in[2];
    const float* Wv = (const float*)d_in[3];
    const float* Wo = (const float*)d_in[4];
    const float* bo = (const float*)d_in[5];
    float* out = (float*)d_out;

    __nv_bfloat16 *xhi, *xlo, *wohi, *wolo;
    cudaGetSymbolAddress((void**)&xhi,  g_xhi);
    cudaGetSymbolAddress((void**)&xlo,  g_xlo);
    cudaGetSymbolAddress((void**)&wohi, g_wohi);
    cudaGetSymbolAddress((void**)&wolo, g_wolo);

    split_kernel<<<(B_ * T_ * C_ / 4 + 255) / 256, 256>>>(x, xhi, xlo, B_ * T_ * C_ / 4);
    split_wqkv_kernel<<<dim3(HS_ * C_ / 256, 48), 256>>>(Wq, Wk, Wv);
    split_kernel<<<(C_ * C_ / 4 + 255) / 256, 256>>>(Wo, wohi, wolo, C_ * C_ / 4);

    qkv_mma_kernel<<<dim3(B_ * T_ / 128, 48), 256>>>();

    attn_hmma_kernel<<<dim3(T_ / 64, B_ * H_), 128>>>();

    proj_mma_kernel<<<dim3(B_ * T_ / 128, C_ / 64), 256>>>(bo, out);
}